// round 16
// baseline (speedup 1.0000x reference)
#include <cuda_runtime.h>
#include <cuda_fp16.h>
#include <math.h>

#define HDIM 256
#define F_IN 128
#define NMAX 100000
#define EMAX 1600000
#define ETOT (4 * EMAX)
#define EPS 1e-5f

// Scratch (allocation-free rule: __device__ globals)
__device__ __half g_xh[(size_t)NMAX * F_IN];     // x in fp16 (gather-1 source)
__device__ __half g_aggh[(size_t)NMAX * F_IN];   // layer-1 aggregate fp16 (GEMM1 A)
__device__ __half g_h1h[(size_t)NMAX * HDIM];    // GEMM1 output fp16 (GEMM2 A)
__device__ __half g_h2h[(size_t)NMAX * HDIM];    // GEMM2 output fp16 (gather-2 source)
__device__ __half g_hout[(size_t)NMAX * HDIM];   // gather-2 output fp16 (pre-LN2)
__device__ float  g_avec[HDIM];
__device__ float  g_dvec[HDIM];                  // c @ W2
__device__ unsigned g_edges[ETOT] __attribute__((aligned(16)));  // packed: src<<15 | q15(w)
__device__ int    g_rowptr[NMAX + 1];
__device__ int    g_pos[NMAX];
__device__ int    g_deg[NMAX];
__device__ int    g_bsum[128];
__device__ double g_scal[4];                     // [sum, sumsq] x 2 layers

// ---- packed f32x2 helpers (B300: 2x fp32 FMA rate, PTX-only pattern) ----
__device__ __forceinline__ unsigned long long pk2(float x, float y) {
    unsigned long long r;
    asm("mov.b64 %0, {%1, %2};" : "=l"(r) : "f"(x), "f"(y));
    return r;
}
__device__ __forceinline__ void upk2(unsigned long long v, float& x, float& y) {
    asm("mov.b64 {%0, %1}, %2;" : "=f"(x), "=f"(y) : "l"(v));
}
__device__ __forceinline__ unsigned long long ffma2(unsigned long long a,
                                                    unsigned long long b,
                                                    unsigned long long c) {
    unsigned long long d;
    asm("fma.rn.f32x2 %0, %1, %2, %3;" : "=l"(d) : "l"(a), "l"(b), "l"(c));
    return d;
}

// Packed edge decode: src = rec>>15, w = (rec & 0x7FFF) / 32767
#define WQ_SCALE (1.0f / 32767.0f)
__device__ __forceinline__ void edec(unsigned r, int& s, float& w) {
    s = (int)(r >> 15);
    w = (float)(int)(r & 0x7FFFu) * WQ_SCALE;
}

// Fused: float->half convert of x AND zero deg.
__global__ __launch_bounds__(256) void k_convert_zdeg(const float* __restrict__ in,
                                                      __half* __restrict__ out, int n2,
                                                      int* __restrict__ deg, int N) {
    int i = blockIdx.x * blockDim.x + threadIdx.x;
    if (i < n2) {
        float2 v = __ldcs(&((const float2*)in)[i]);
        ((__half2*)out)[i] = __floats2half2_rn(v.x, v.y);
    }
    if (i < N) deg[i] = 0;
}

// Histogram over all 4 relations in one kernel.
__global__ __launch_bounds__(256) void k_hist_all(const int* __restrict__ e0,
                                                  const int* __restrict__ e1,
                                                  const int* __restrict__ e2,
                                                  const int* __restrict__ e3,
                                                  int* __restrict__ deg, int E) {
    int t = blockIdx.x * blockDim.x + threadIdx.x;
    const int* p;
    if (t < E) p = e0;
    else if (t < 2 * E) { p = e1; t -= E; }
    else if (t < 3 * E) { p = e2; t -= 2 * E; }
    else if (t < 4 * E) { p = e3; t -= 3 * E; }
    else return;
    atomicAdd(&deg[__ldcs(&p[E + t])], 1);
}

// Scan phase 1 (+ zero g_scal).
__global__ __launch_bounds__(1024) void k_scan1z(const int* __restrict__ deg,
                                                 int* __restrict__ rowptr, int N) {
    __shared__ int sh[1024];
    int tid = threadIdx.x;
    if (blockIdx.x == 0 && tid < 4) g_scal[tid] = 0.0;
    int i = blockIdx.x * 1024 + tid;
    int v = (i < N) ? deg[i] : 0;
    sh[tid] = v;
    __syncthreads();
    for (int o = 1; o < 1024; o <<= 1) {
        int t = (tid >= o) ? sh[tid - o] : 0;
        __syncthreads();
        sh[tid] += t;
        __syncthreads();
    }
    if (i < N) rowptr[i] = sh[tid] - v;
    if (tid == 1023) g_bsum[blockIdx.x] = sh[1023];
}

// Scan phase 2+3 fused: each block reduces bsum[0..bid) itself.
__global__ __launch_bounds__(1024) void k_scan3b(int* __restrict__ rowptr,
                                                 int* __restrict__ pos,
                                                 const int* __restrict__ deg, int N) {
    __shared__ int sh[128];
    __shared__ int off;
    int tid = threadIdx.x;
    int bid = blockIdx.x;
    if (tid < 128) {
        int partial = 0;
        for (int j = tid; j < bid; j += 128) partial += g_bsum[j];
        sh[tid] = partial;
    }
    __syncthreads();
    if (tid == 0) {
        int s = 0;
        for (int j = 0; j < 128; j++) s += sh[j];
        off = s;
    }
    __syncthreads();
    int i = bid * 1024 + tid;
    if (i < N) {
        int r = rowptr[i] + off;
        rowptr[i] = r;
        pos[i] = r;
        if (i == N - 1) rowptr[N] = r + deg[i];
    }
}

// Fill packed CSR payload for all 4 relations in one kernel.
__global__ __launch_bounds__(256) void k_fill_all(const int* __restrict__ e0,
                                                  const float* __restrict__ w0,
                                                  const int* __restrict__ e1,
                                                  const float* __restrict__ w1,
                                                  const int* __restrict__ e2,
                                                  const float* __restrict__ w2,
                                                  const int* __restrict__ e3,
                                                  const float* __restrict__ w3,
                                                  int* __restrict__ pos, int E) {
    int t = blockIdx.x * blockDim.x + threadIdx.x;
    const int* p;
    const float* w;
    if (t < E) { p = e0; w = w0; }
    else if (t < 2 * E) { p = e1; w = w1; t -= E; }
    else if (t < 3 * E) { p = e2; w = w2; t -= 2 * E; }
    else if (t < 4 * E) { p = e3; w = w3; t -= 3 * E; }
    else return;
    int dst = __ldcs(&p[E + t]);
    int q = atomicAdd(&pos[dst], 1);
    int wq = __float2int_rn(__ldcs(&w[t]) * 32767.0f);
    wq = min(max(wq, 0), 32767);
    unsigned rec = ((unsigned)__ldcs(&p[t]) << 15) | (unsigned)wq;
    g_edges[q] = rec;
}

__device__ __forceinline__ float4 fma4_u2(float4 acc, unsigned lo, unsigned hi, float w) {
    float2 f0 = __half22float2(*(__half2*)&lo);
    float2 f1 = __half22float2(*(__half2*)&hi);
    acc.x += w * f0.x; acc.y += w * f0.y;
    acc.z += w * f1.x; acc.w += w * f1.y;
    return acc;
}

// Layer-1 gather: aggh[n, 0:128] = fp16(sum_e w * xh[src]). 1 warp/node, 2/block.
__global__ __launch_bounds__(64) void k_gather1(const uint2* __restrict__ X,
                                                const int* __restrict__ rowptr,
                                                __half* __restrict__ aggh, int N) {
    int n = blockIdx.x * 2 + (threadIdx.x >> 5);
    if (n >= N) return;
    int t = threadIdx.x & 31;
    int e = __ldg(&rowptr[n]);
    int e1 = __ldg(&rowptr[n + 1]);
    float4 acc = make_float4(0.f, 0.f, 0.f, 0.f);
    while (e < e1 && (e & 3)) {
        int s; float w;
        edec(__ldcs(&g_edges[e]), s, w);
        uint2 u = __ldg(&X[(size_t)s * 32 + t]);
        acc = fma4_u2(acc, u.x, u.y, w);
        e++;
    }
    for (; e + 4 <= e1; e += 4) {
        uint4 rr = __ldcs((const uint4*)&g_edges[e]);
        int s0, s1, s2, s3; float w0, w1, w2, w3;
        edec(rr.x, s0, w0); edec(rr.y, s1, w1);
        edec(rr.z, s2, w2); edec(rr.w, s3, w3);
        uint2 u0 = __ldg(&X[(size_t)s0 * 32 + t]);
        uint2 u1 = __ldg(&X[(size_t)s1 * 32 + t]);
        uint2 u2 = __ldg(&X[(size_t)s2 * 32 + t]);
        uint2 u3 = __ldg(&X[(size_t)s3 * 32 + t]);
        acc = fma4_u2(acc, u0.x, u0.y, w0);
        acc = fma4_u2(acc, u1.x, u1.y, w1);
        acc = fma4_u2(acc, u2.x, u2.y, w2);
        acc = fma4_u2(acc, u3.x, u3.y, w3);
    }
    for (; e < e1; e++) {
        int s; float w;
        edec(__ldcs(&g_edges[e]), s, w);
        uint2 u = __ldg(&X[(size_t)s * 32 + t]);
        acc = fma4_u2(acc, u.x, u.y, w);
    }
    __half2 h0 = __floats2half2_rn(acc.x, acc.y);
    __half2 h1 = __floats2half2_rn(acc.z, acc.w);
    uint2 pk;
    pk.x = *(unsigned*)&h0;
    pk.y = *(unsigned*)&h1;
    __stcs((uint2*)(aggh + (size_t)n * F_IN + 4 * t), pk);
}

// Layer-2 gather: hout[n] = fp16(b2 + sum_e w * h2h[src]); LN stats -> g_scal[2,3].
__global__ __launch_bounds__(64) void k_gather2(const uint4* __restrict__ H,
                                                const int* __restrict__ rowptr,
                                                const float* __restrict__ bias,
                                                __half* __restrict__ hout, int N) {
    int n = blockIdx.x * 2 + (threadIdx.x >> 5);
    if (n >= N) return;
    int t = threadIdx.x & 31;
    int e = __ldg(&rowptr[n]);
    int e1 = __ldg(&rowptr[n + 1]);
    float4 a01 = __ldg(&((const float4*)bias)[2 * t]);
    float4 a23 = __ldg(&((const float4*)bias)[2 * t + 1]);
    while (e < e1 && (e & 3)) {
        int s; float w;
        edec(__ldcs(&g_edges[e]), s, w);
        uint4 u = __ldg(&H[(size_t)s * 32 + t]);
        a01 = fma4_u2(a01, u.x, u.y, w);
        a23 = fma4_u2(a23, u.z, u.w, w);
        e++;
    }
    for (; e + 4 <= e1; e += 4) {
        uint4 rr = __ldcs((const uint4*)&g_edges[e]);
        int s0, s1, s2, s3; float w0, w1, w2, w3;
        edec(rr.x, s0, w0); edec(rr.y, s1, w1);
        edec(rr.z, s2, w2); edec(rr.w, s3, w3);
        uint4 u0 = __ldg(&H[(size_t)s0 * 32 + t]);
        uint4 u1 = __ldg(&H[(size_t)s1 * 32 + t]);
        uint4 u2 = __ldg(&H[(size_t)s2 * 32 + t]);
        uint4 u3 = __ldg(&H[(size_t)s3 * 32 + t]);
        a01 = fma4_u2(a01, u0.x, u0.y, w0); a23 = fma4_u2(a23, u0.z, u0.w, w0);
        a01 = fma4_u2(a01, u1.x, u1.y, w1); a23 = fma4_u2(a23, u1.z, u1.w, w1);
        a01 = fma4_u2(a01, u2.x, u2.y, w2); a23 = fma4_u2(a23, u2.z, u2.w, w2);
        a01 = fma4_u2(a01, u3.x, u3.y, w3); a23 = fma4_u2(a23, u3.z, u3.w, w3);
    }
    for (; e < e1; e++) {
        int s; float w;
        edec(__ldcs(&g_edges[e]), s, w);
        uint4 u = __ldg(&H[(size_t)s * 32 + t]);
        a01 = fma4_u2(a01, u.x, u.y, w);
        a23 = fma4_u2(a23, u.z, u.w, w);
    }
    __half2 h0 = __floats2half2_rn(a01.x, a01.y);
    __half2 h1 = __floats2half2_rn(a01.z, a01.w);
    __half2 h2 = __floats2half2_rn(a23.x, a23.y);
    __half2 h3 = __floats2half2_rn(a23.z, a23.w);
    uint4 pk;
    pk.x = *(unsigned*)&h0; pk.y = *(unsigned*)&h1;
    pk.z = *(unsigned*)&h2; pk.w = *(unsigned*)&h3;
    __stcs((uint4*)(hout + (size_t)n * HDIM) + t, pk);
    double s = (double)a01.x + a01.y + a01.z + a01.w +
               (double)a23.x + a23.y + a23.z + a23.w;
    double q = (double)a01.x * a01.x + (double)a01.y * a01.y +
               (double)a01.z * a01.z + (double)a01.w * a01.w +
               (double)a23.x * a23.x + (double)a23.y * a23.y +
               (double)a23.z * a23.z + (double)a23.w * a23.w;
    for (int o = 16; o > 0; o >>= 1) {
        s += __shfl_xor_sync(0xFFFFFFFFu, s, o);
        q += __shfl_xor_sync(0xFFFFFFFFu, q, o);
    }
    if (t == 0) {
        atomicAdd(&g_scal[2], s);
        atomicAdd(&g_scal[3], q);
    }
}

// ---- Big-tile GEMM, fp16 A, double-buffered SMEM, packed f32x2 FMA ----
// SCALEB: scale B row k by g_avec[k] at stage time (LN1 fold, no W2f copy).
template<int K, int ASTR, bool EPI1, bool SCALEB>
__global__ __launch_bounds__(256) void k_gemm_big(const __half* __restrict__ Ah,
                                                  const float* __restrict__ B,
                                                  const float* __restrict__ bias,
                                                  __half* __restrict__ C, int M) {
    __shared__ float sA[2][16 * 136];
    __shared__ float sB[2][16 * 132];
    __shared__ double sds[512];
    const int NT = K / 16;
    int tid = threadIdx.x;
    int tx = tid & 15, ty = tid >> 4;
    int m0 = blockIdx.y * 128, n0 = blockIdx.x * 128;

    unsigned long long acc[8][4];
#pragma unroll
    for (int i = 0; i < 8; i++)
#pragma unroll
        for (int j = 0; j < 4; j++) acc[i][j] = 0ull;

    int fa0 = tid, fa1 = 256 + tid;
    int ar0 = fa0 >> 2, ac0 = (fa0 & 3) * 4;
    int ar1 = fa1 >> 2, ac1 = (fa1 & 3) * 4;
    int br0 = (tid) >> 5, bc0 = (tid & 31) * 4;
    int br1 = (256 + tid) >> 5, bc1 = ((256 + tid) & 31) * 4;

    uint2 aL0, aL1;
    float4 bL0, bL1;
    auto loadg = [&](int k0) {
        aL0 = (m0 + ar0 < M)
                  ? *(const uint2*)(Ah + (size_t)(m0 + ar0) * ASTR + k0 + ac0)
                  : make_uint2(0u, 0u);
        aL1 = (m0 + ar1 < M)
                  ? *(const uint2*)(Ah + (size_t)(m0 + ar1) * ASTR + k0 + ac1)
                  : make_uint2(0u, 0u);
        bL0 = *(const float4*)(B + (size_t)(k0 + br0) * HDIM + n0 + bc0);
        bL1 = *(const float4*)(B + (size_t)(k0 + br1) * HDIM + n0 + bc1);
        if (SCALEB) {
            float s0 = __ldg(&g_avec[k0 + br0]);
            float s1 = __ldg(&g_avec[k0 + br1]);
            bL0.x *= s0; bL0.y *= s0; bL0.z *= s0; bL0.w *= s0;
            bL1.x *= s1; bL1.y *= s1; bL1.z *= s1; bL1.w *= s1;
        }
    };
    auto store_s = [&](int buf) {
        float2 f0 = __half22float2(*(__half2*)&aL0.x);
        float2 f1 = __half22float2(*(__half2*)&aL0.y);
        sA[buf][(ac0 + 0) * 136 + ar0] = f0.x;
        sA[buf][(ac0 + 1) * 136 + ar0] = f0.y;
        sA[buf][(ac0 + 2) * 136 + ar0] = f1.x;
        sA[buf][(ac0 + 3) * 136 + ar0] = f1.y;
        float2 f2 = __half22float2(*(__half2*)&aL1.x);
        float2 f3 = __half22float2(*(__half2*)&aL1.y);
        sA[buf][(ac1 + 0) * 136 + ar1] = f2.x;
        sA[buf][(ac1 + 1) * 136 + ar1] = f2.y;
        sA[buf][(ac1 + 2) * 136 + ar1] = f3.x;
        sA[buf][(ac1 + 3) * 136 + ar1] = f3.y;
        *(float4*)&sB[buf][br0 * 132 + bc0] = bL0;
        *(float4*)&sB[buf][br1 * 132 + bc1] = bL1;
    };

    loadg(0);
    store_s(0);
    __syncthreads();
    int buf = 0;
    for (int kt = 0; kt < NT; kt++) {
        if (kt + 1 < NT) loadg((kt + 1) * 16);
#pragma unroll
        for (int k = 0; k < 16; k++) {
            float4 ra0 = *(const float4*)&sA[buf][k * 136 + ty * 8];
            float4 ra1 = *(const float4*)&sA[buf][k * 136 + ty * 8 + 4];
            ulonglong2 b01 = *(const ulonglong2*)&sB[buf][k * 132 + tx * 8];
            ulonglong2 b23 = *(const ulonglong2*)&sB[buf][k * 132 + tx * 8 + 4];
            float am[8] = {ra0.x, ra0.y, ra0.z, ra0.w, ra1.x, ra1.y, ra1.z, ra1.w};
#pragma unroll
            for (int i = 0; i < 8; i++) {
                unsigned long long pa = pk2(am[i], am[i]);
                acc[i][0] = ffma2(pa, b01.x, acc[i][0]);
                acc[i][1] = ffma2(pa, b01.y, acc[i][1]);
                acc[i][2] = ffma2(pa, b23.x, acc[i][2]);
                acc[i][3] = ffma2(pa, b23.y, acc[i][3]);
            }
        }
        if (kt + 1 < NT) {
            store_s(buf ^ 1);
            __syncthreads();
            buf ^= 1;
        }
    }

    float bv[8];
#pragma unroll
    for (int j = 0; j < 4; j++) {
        float2 b2 = *(const float2*)(bias + n0 + tx * 8 + j * 2);
        bv[2 * j] = b2.x;
        bv[2 * j + 1] = b2.y;
    }
    float s = 0.f, q = 0.f;
#pragma unroll
    for (int i = 0; i < 8; i++) {
        int row = m0 + ty * 8 + i;
        if (row < M) {
            __half2* dst = (__half2*)(C + (size_t)row * HDIM + n0 + tx * 8);
#pragma unroll
            for (int j = 0; j < 4; j++) {
                float lo, hi;
                upk2(acc[i][j], lo, hi);
                lo += bv[2 * j];
                hi += bv[2 * j + 1];
                dst[j] = __floats2half2_rn(lo, hi);
                if (EPI1) {
                    s += lo + hi;
                    q += lo * lo + hi * hi;
                }
            }
        }
    }
    if (EPI1) {
        sds[tid] = (double)s;
        sds[256 + tid] = (double)q;
        __syncthreads();
        for (int o = 128; o > 0; o >>= 1) {
            if (tid < o) {
                sds[tid] += sds[tid + o];
                sds[256 + tid] += sds[256 + tid + o];
            }
            __syncthreads();
        }
        if (tid == 0) {
            atomicAdd(&g_scal[0], sds[0]);
            atomicAdd(&g_scal[1], sds[256]);
        }
    }
}

// Fold LN1 into W2: a_k = inv*ln1w_k; c_k = ln1b_k - mean*a_k; d = c @ W2.
__global__ __launch_bounds__(256) void k_prep(const float* __restrict__ lnw,
                                              const float* __restrict__ lnb,
                                              const float* __restrict__ W2, int M) {
    __shared__ float cs[HDIM];
    int t = threadIdx.x;
    double nn = (double)M * HDIM;
    double mm = g_scal[0] / nn;
    double var = g_scal[1] / nn - mm * mm;
    float mean = (float)mm;
    float inv = 1.f / ((float)sqrt(var) + EPS);
    float a = inv * lnw[t];
    float c = lnb[t] - mean * a;
    g_avec[t] = a;
    cs[t] = c;
    __syncthreads();
    float d = 0.f;
    for (int k = 0; k < HDIM; k++) d += cs[k] * W2[k * HDIM + t];
    g_dvec[t] = d;
}

// Final graph LayerNorm: read fp16 hout, write fp32 out (evict-first).
__global__ __launch_bounds__(256) void k_ln2h(const __half* __restrict__ hout,
                                              const float* __restrict__ w,
                                              const float* __restrict__ b,
                                              float* __restrict__ out, int n8) {
    int i = blockIdx.x * blockDim.x + threadIdx.x;
    if (i >= n8) return;
    double n = (double)n8 * 8.0;
    double m = g_scal[2] / n;
    double var = g_scal[3] / n - m * m;
    float mean = (float)m;
    float inv = 1.f / ((float)sqrt(var) + EPS);
    uint4 u = __ldcs((const uint4*)hout + i);
    int c8 = (i & 31) * 8;
    float4 w0 = *(const float4*)(w + c8);
    float4 w1 = *(const float4*)(w + c8 + 4);
    float4 b0 = *(const float4*)(b + c8);
    float4 b1 = *(const float4*)(b + c8 + 4);
    float2 f0 = __half22float2(*(__half2*)&u.x);
    float2 f1 = __half22float2(*(__half2*)&u.y);
    float2 f2 = __half22float2(*(__half2*)&u.z);
    float2 f3 = __half22float2(*(__half2*)&u.w);
    float4 o0, o1;
    o0.x = (f0.x - mean) * inv * w0.x + b0.x;
    o0.y = (f0.y - mean) * inv * w0.y + b0.y;
    o0.z = (f1.x - mean) * inv * w0.z + b0.z;
    o0.w = (f1.y - mean) * inv * w0.w + b0.w;
    o1.x = (f2.x - mean) * inv * w1.x + b1.x;
    o1.y = (f2.y - mean) * inv * w1.y + b1.y;
    o1.z = (f3.x - mean) * inv * w1.z + b1.z;
    o1.w = (f3.y - mean) * inv * w1.w + b1.w;
    __stcs((float4*)out + 2 * i, o0);
    __stcs((float4*)out + 2 * i + 1, o1);
}

extern "C" void kernel_launch(void* const* d_in, const int* in_sizes, int n_in,
                              void* d_out, int out_size) {
    const float* x = (const float*)d_in[0];
    const int* ei[4] = {(const int*)d_in[1], (const int*)d_in[3],
                        (const int*)d_in[5], (const int*)d_in[7]};
    const float* ew[4] = {(const float*)d_in[2], (const float*)d_in[4],
                          (const float*)d_in[6], (const float*)d_in[8]};
    const float* W1 = (const float*)d_in[9];
    const float* b1 = (const float*)d_in[10];
    const float* W2 = (const float*)d_in[11];
    const float* b2 = (const float*)d_in[12];
    const float* ln1w = (const float*)d_in[13];
    const float* ln1b = (const float*)d_in[14];
    const float* ln2w = (const float*)d_in[15];
    const float* ln2b = (const float*)d_in[16];

    int N = in_sizes[0] / F_IN;
    int E = in_sizes[1] / 2;
    int n2 = N * F_IN / 2;
    int n8 = N * HDIM / 8;

    __half *xh, *aggh, *h1h, *h2h, *hout;
    float *dvec;
    int *rowptr, *pos, *deg;
    cudaGetSymbolAddress((void**)&xh, g_xh);
    cudaGetSymbolAddress((void**)&aggh, g_aggh);
    cudaGetSymbolAddress((void**)&h1h, g_h1h);
    cudaGetSymbolAddress((void**)&h2h, g_h2h);
    cudaGetSymbolAddress((void**)&hout, g_hout);
    cudaGetSymbolAddress((void**)&dvec, g_dvec);
    cudaGetSymbolAddress((void**)&rowptr, g_rowptr);
    cudaGetSymbolAddress((void**)&pos, g_pos);
    cudaGetSymbolAddress((void**)&deg, g_deg);
    float* out = (float*)d_out;

    int e4Blocks = (4 * E + 255) / 256;
    int scanB = (N + 1023) / 1024;
    dim3 gbig(HDIM / 128, (N + 127) / 128);

    k_convert_zdeg<<<(n2 + 255) / 256, 256>>>(x, xh, n2, deg, N);
    k_hist_all<<<e4Blocks, 256>>>(ei[0], ei[1], ei[2], ei[3], deg, E);
    k_scan1z<<<scanB, 1024>>>(deg, rowptr, N);
    k_scan3b<<<scanB, 1024>>>(rowptr, pos, deg, N);
    k_fill_all<<<e4Blocks, 256>>>(ei[0], ew[0], ei[1], ew[1], ei[2], ew[2],
                                  ei[3], ew[3], pos, E);
    k_gather1<<<(N + 1) / 2, 64>>>((const uint2*)xh, rowptr, aggh, N);
    k_gemm_big<F_IN, F_IN, true, false><<<gbig, 256>>>(aggh, W1, b1, h1h, N);
    k_prep<<<1, 256>>>(ln1w, ln1b, W2, N);
    k_gemm_big<HDIM, HDIM, false, true><<<gbig, 256>>>(h1h, W2, dvec, h2h, N);
    k_gather2<<<(N + 1) / 2, 64>>>((const uint4*)h2h, rowptr, b2, hout, N);
    k_ln2h<<<(n8 + 255) / 256, 256>>>(hout, ln2w, ln2b, out, n8);
}

// round 17
// speedup vs baseline: 1.2995x; 1.2995x over previous
#include <cuda_runtime.h>
#include <cuda_fp16.h>
#include <math.h>

#define HDIM 256
#define F_IN 128
#define NMAX 100000
#define EMAX 1600000
#define ETOT (4 * EMAX)
#define EPS 1e-5f

// Scratch (allocation-free rule: __device__ globals)
__device__ __half g_xh[(size_t)NMAX * F_IN];     // x in fp16 (gather-1 source)
__device__ __half g_aggh[(size_t)NMAX * F_IN];   // agg1 = Adj@x, fp16 (GEMM1-stats A + gather-2 table)
__device__ __half g_agg2h[(size_t)NMAX * F_IN];  // agg2 = Adj@agg1, fp16 (final GEMM A)
__device__ __half g_hout[(size_t)NMAX * HDIM];   // final GEMM output fp16 (pre-LN2)
__device__ float  g_degw[NMAX];                  // per-node sum of edge weights
__device__ float  g_Wc[F_IN * HDIM];             // W1 · diag(a) · W2
__device__ float  g_avec[HDIM];
__device__ float  g_dvec[HDIM];                  // v = (a∘b1+c) @ W2
__device__ unsigned g_edges[ETOT] __attribute__((aligned(16)));  // packed: src<<15 | q15(w)
__device__ int    g_rowptr[NMAX + 1];
__device__ int    g_pos[NMAX];
__device__ int    g_deg[NMAX];
__device__ int    g_bsum[128];
__device__ double g_scal[4];                     // [sum, sumsq] x 2 layers

// ---- packed f32x2 helpers (B300: 2x fp32 FMA rate, PTX-only pattern) ----
__device__ __forceinline__ unsigned long long pk2(float x, float y) {
    unsigned long long r;
    asm("mov.b64 %0, {%1, %2};" : "=l"(r) : "f"(x), "f"(y));
    return r;
}
__device__ __forceinline__ void upk2(unsigned long long v, float& x, float& y) {
    asm("mov.b64 {%0, %1}, %2;" : "=f"(x), "=f"(y) : "l"(v));
}
__device__ __forceinline__ unsigned long long ffma2(unsigned long long a,
                                                    unsigned long long b,
                                                    unsigned long long c) {
    unsigned long long d;
    asm("fma.rn.f32x2 %0, %1, %2, %3;" : "=l"(d) : "l"(a), "l"(b), "l"(c));
    return d;
}

// Packed edge decode: src = rec>>15, w = (rec & 0x7FFF) / 32767
#define WQ_SCALE (1.0f / 32767.0f)
__device__ __forceinline__ void edec(unsigned r, int& s, float& w) {
    s = (int)(r >> 15);
    w = (float)(int)(r & 0x7FFFu) * WQ_SCALE;
}

// Fused: float->half convert of x AND zero deg.
__global__ __launch_bounds__(256) void k_convert_zdeg(const float* __restrict__ in,
                                                      __half* __restrict__ out, int n2,
                                                      int* __restrict__ deg, int N) {
    int i = blockIdx.x * blockDim.x + threadIdx.x;
    if (i < n2) {
        float2 v = __ldcs(&((const float2*)in)[i]);
        ((__half2*)out)[i] = __floats2half2_rn(v.x, v.y);
    }
    if (i < N) deg[i] = 0;
}

// Histogram over all 4 relations in one kernel.
__global__ __launch_bounds__(256) void k_hist_all(const int* __restrict__ e0,
                                                  const int* __restrict__ e1,
                                                  const int* __restrict__ e2,
                                                  const int* __restrict__ e3,
                                                  int* __restrict__ deg, int E) {
    int t = blockIdx.x * blockDim.x + threadIdx.x;
    const int* p;
    if (t < E) p = e0;
    else if (t < 2 * E) { p = e1; t -= E; }
    else if (t < 3 * E) { p = e2; t -= 2 * E; }
    else if (t < 4 * E) { p = e3; t -= 3 * E; }
    else return;
    atomicAdd(&deg[__ldcs(&p[E + t])], 1);
}

// Scan phase 1 (+ zero g_scal).
__global__ __launch_bounds__(1024) void k_scan1z(const int* __restrict__ deg,
                                                 int* __restrict__ rowptr, int N) {
    __shared__ int sh[1024];
    int tid = threadIdx.x;
    if (blockIdx.x == 0 && tid < 4) g_scal[tid] = 0.0;
    int i = blockIdx.x * 1024 + tid;
    int v = (i < N) ? deg[i] : 0;
    sh[tid] = v;
    __syncthreads();
    for (int o = 1; o < 1024; o <<= 1) {
        int t = (tid >= o) ? sh[tid - o] : 0;
        __syncthreads();
        sh[tid] += t;
        __syncthreads();
    }
    if (i < N) rowptr[i] = sh[tid] - v;
    if (tid == 1023) g_bsum[blockIdx.x] = sh[1023];
}

// Scan phase 2+3 fused: each block reduces bsum[0..bid) itself.
__global__ __launch_bounds__(1024) void k_scan3b(int* __restrict__ rowptr,
                                                 int* __restrict__ pos,
                                                 const int* __restrict__ deg, int N) {
    __shared__ int sh[128];
    __shared__ int off;
    int tid = threadIdx.x;
    int bid = blockIdx.x;
    if (tid < 128) {
        int partial = 0;
        for (int j = tid; j < bid; j += 128) partial += g_bsum[j];
        sh[tid] = partial;
    }
    __syncthreads();
    if (tid == 0) {
        int s = 0;
        for (int j = 0; j < 128; j++) s += sh[j];
        off = s;
    }
    __syncthreads();
    int i = bid * 1024 + tid;
    if (i < N) {
        int r = rowptr[i] + off;
        rowptr[i] = r;
        pos[i] = r;
        if (i == N - 1) rowptr[N] = r + deg[i];
    }
}

// Fill packed CSR payload for all 4 relations in one kernel.
__global__ __launch_bounds__(256) void k_fill_all(const int* __restrict__ e0,
                                                  const float* __restrict__ w0,
                                                  const int* __restrict__ e1,
                                                  const float* __restrict__ w1,
                                                  const int* __restrict__ e2,
                                                  const float* __restrict__ w2,
                                                  const int* __restrict__ e3,
                                                  const float* __restrict__ w3,
                                                  int* __restrict__ pos, int E) {
    int t = blockIdx.x * blockDim.x + threadIdx.x;
    const int* p;
    const float* w;
    if (t < E) { p = e0; w = w0; }
    else if (t < 2 * E) { p = e1; w = w1; t -= E; }
    else if (t < 3 * E) { p = e2; w = w2; t -= 2 * E; }
    else if (t < 4 * E) { p = e3; w = w3; t -= 3 * E; }
    else return;
    int dst = __ldcs(&p[E + t]);
    int q = atomicAdd(&pos[dst], 1);
    int wq = __float2int_rn(__ldcs(&w[t]) * 32767.0f);
    wq = min(max(wq, 0), 32767);
    unsigned rec = ((unsigned)__ldcs(&p[t]) << 15) | (unsigned)wq;
    g_edges[q] = rec;
}

__device__ __forceinline__ float4 fma4_u2(float4 acc, unsigned lo, unsigned hi, float w) {
    float2 f0 = __half22float2(*(__half2*)&lo);
    float2 f1 = __half22float2(*(__half2*)&hi);
    acc.x += w * f0.x; acc.y += w * f0.y;
    acc.z += w * f1.x; acc.w += w * f1.y;
    return acc;
}

// 128-d gather: dst16[n] = fp16(sum_e w * X[src]); optionally degw[n] = sum_e w.
// 1 warp/node, 2 nodes/block, uint2 (4 fp16 ch) per lane.
template<bool DEGW>
__global__ __launch_bounds__(64) void k_gather128(const uint2* __restrict__ X,
                                                  const int* __restrict__ rowptr,
                                                  __half* __restrict__ dst16,
                                                  float* __restrict__ degw, int N) {
    int n = blockIdx.x * 2 + (threadIdx.x >> 5);
    if (n >= N) return;
    int t = threadIdx.x & 31;
    int e = __ldg(&rowptr[n]);
    int e1 = __ldg(&rowptr[n + 1]);
    float4 acc = make_float4(0.f, 0.f, 0.f, 0.f);
    float ws = 0.f;
    while (e < e1 && (e & 3)) {
        int s; float w;
        edec(__ldcs(&g_edges[e]), s, w);
        uint2 u = __ldg(&X[(size_t)s * 32 + t]);
        acc = fma4_u2(acc, u.x, u.y, w);
        if (DEGW) ws += w;
        e++;
    }
    for (; e + 4 <= e1; e += 4) {
        uint4 rr = __ldcs((const uint4*)&g_edges[e]);
        int s0, s1, s2, s3; float w0, w1, w2, w3;
        edec(rr.x, s0, w0); edec(rr.y, s1, w1);
        edec(rr.z, s2, w2); edec(rr.w, s3, w3);
        uint2 u0 = __ldg(&X[(size_t)s0 * 32 + t]);
        uint2 u1 = __ldg(&X[(size_t)s1 * 32 + t]);
        uint2 u2 = __ldg(&X[(size_t)s2 * 32 + t]);
        uint2 u3 = __ldg(&X[(size_t)s3 * 32 + t]);
        acc = fma4_u2(acc, u0.x, u0.y, w0);
        acc = fma4_u2(acc, u1.x, u1.y, w1);
        acc = fma4_u2(acc, u2.x, u2.y, w2);
        acc = fma4_u2(acc, u3.x, u3.y, w3);
        if (DEGW) ws += w0 + w1 + w2 + w3;
    }
    for (; e < e1; e++) {
        int s; float w;
        edec(__ldcs(&g_edges[e]), s, w);
        uint2 u = __ldg(&X[(size_t)s * 32 + t]);
        acc = fma4_u2(acc, u.x, u.y, w);
        if (DEGW) ws += w;
    }
    __half2 h0 = __floats2half2_rn(acc.x, acc.y);
    __half2 h1 = __floats2half2_rn(acc.z, acc.w);
    uint2 pk;
    pk.x = *(unsigned*)&h0;
    pk.y = *(unsigned*)&h1;
    __stcs((uint2*)(dst16 + (size_t)n * F_IN + 4 * t), pk);
    if (DEGW && t == 0) degw[n] = ws;
}

// ---- Big-tile GEMM, fp16 A (stride K), double-buffered SMEM, packed f32x2 FMA ----
// STORE_C: write fp16 C.  STAT>=0: LN stats into g_scal[STAT,STAT+1].
// FINAL: add degw[row]*vvec[col] to the bias term.
template<int K, bool STORE_C, int STAT, bool FINAL>
__global__ __launch_bounds__(256) void k_gemm_big(const __half* __restrict__ Ah,
                                                  const float* __restrict__ B,
                                                  const float* __restrict__ bias,
                                                  const float* __restrict__ degw,
                                                  const float* __restrict__ vvec,
                                                  __half* __restrict__ C, int M) {
    __shared__ float sA[2][16 * 136];
    __shared__ float sB[2][16 * 132];
    __shared__ double sds[512];
    const int NT = K / 16;
    int tid = threadIdx.x;
    int tx = tid & 15, ty = tid >> 4;
    int m0 = blockIdx.y * 128, n0 = blockIdx.x * 128;

    unsigned long long acc[8][4];
#pragma unroll
    for (int i = 0; i < 8; i++)
#pragma unroll
        for (int j = 0; j < 4; j++) acc[i][j] = 0ull;

    int fa0 = tid, fa1 = 256 + tid;
    int ar0 = fa0 >> 2, ac0 = (fa0 & 3) * 4;
    int ar1 = fa1 >> 2, ac1 = (fa1 & 3) * 4;
    int br0 = (tid) >> 5, bc0 = (tid & 31) * 4;
    int br1 = (256 + tid) >> 5, bc1 = ((256 + tid) & 31) * 4;

    uint2 aL0, aL1;
    float4 bL0, bL1;
    auto loadg = [&](int k0) {
        aL0 = (m0 + ar0 < M)
                  ? *(const uint2*)(Ah + (size_t)(m0 + ar0) * K + k0 + ac0)
                  : make_uint2(0u, 0u);
        aL1 = (m0 + ar1 < M)
                  ? *(const uint2*)(Ah + (size_t)(m0 + ar1) * K + k0 + ac1)
                  : make_uint2(0u, 0u);
        bL0 = *(const float4*)(B + (size_t)(k0 + br0) * HDIM + n0 + bc0);
        bL1 = *(const float4*)(B + (size_t)(k0 + br1) * HDIM + n0 + bc1);
    };
    auto store_s = [&](int buf) {
        float2 f0 = __half22float2(*(__half2*)&aL0.x);
        float2 f1 = __half22float2(*(__half2*)&aL0.y);
        sA[buf][(ac0 + 0) * 136 + ar0] = f0.x;
        sA[buf][(ac0 + 1) * 136 + ar0] = f0.y;
        sA[buf][(ac0 + 2) * 136 + ar0] = f1.x;
        sA[buf][(ac0 + 3) * 136 + ar0] = f1.y;
        float2 f2 = __half22float2(*(__half2*)&aL1.x);
        float2 f3 = __half22float2(*(__half2*)&aL1.y);
        sA[buf][(ac1 + 0) * 136 + ar1] = f2.x;
        sA[buf][(ac1 + 1) * 136 + ar1] = f2.y;
        sA[buf][(ac1 + 2) * 136 + ar1] = f3.x;
        sA[buf][(ac1 + 3) * 136 + ar1] = f3.y;
        *(float4*)&sB[buf][br0 * 132 + bc0] = bL0;
        *(float4*)&sB[buf][br1 * 132 + bc1] = bL1;
    };

    loadg(0);
    store_s(0);
    __syncthreads();
    int buf = 0;
    for (int kt = 0; kt < NT; kt++) {
        if (kt + 1 < NT) loadg((kt + 1) * 16);
#pragma unroll
        for (int k = 0; k < 16; k++) {
            float4 ra0 = *(const float4*)&sA[buf][k * 136 + ty * 8];
            float4 ra1 = *(const float4*)&sA[buf][k * 136 + ty * 8 + 4];
            ulonglong2 b01 = *(const ulonglong2*)&sB[buf][k * 132 + tx * 8];
            ulonglong2 b23 = *(const ulonglong2*)&sB[buf][k * 132 + tx * 8 + 4];
            float am[8] = {ra0.x, ra0.y, ra0.z, ra0.w, ra1.x, ra1.y, ra1.z, ra1.w};
#pragma unroll
            for (int i = 0; i < 8; i++) {
                unsigned long long pa = pk2(am[i], am[i]);
                acc[i][0] = ffma2(pa, b01.x, acc[i][0]);
                acc[i][1] = ffma2(pa, b01.y, acc[i][1]);
                acc[i][2] = ffma2(pa, b23.x, acc[i][2]);
                acc[i][3] = ffma2(pa, b23.y, acc[i][3]);
            }
        }
        if (kt + 1 < NT) {
            store_s(buf ^ 1);
            __syncthreads();
            buf ^= 1;
        }
    }

    float bv[8], vv[8];
#pragma unroll
    for (int j = 0; j < 4; j++) {
        float2 b2 = *(const float2*)(bias + n0 + tx * 8 + j * 2);
        bv[2 * j] = b2.x;
        bv[2 * j + 1] = b2.y;
        if (FINAL) {
            float2 v2 = *(const float2*)(vvec + n0 + tx * 8 + j * 2);
            vv[2 * j] = v2.x;
            vv[2 * j + 1] = v2.y;
        }
    }
    float s = 0.f, q = 0.f;
#pragma unroll
    for (int i = 0; i < 8; i++) {
        int row = m0 + ty * 8 + i;
        if (row < M) {
            float dw = FINAL ? __ldg(&degw[row]) : 0.f;
            __half2* dst = (__half2*)(C + (size_t)row * HDIM + n0 + tx * 8);
#pragma unroll
            for (int j = 0; j < 4; j++) {
                float lo, hi;
                upk2(acc[i][j], lo, hi);
                lo += bv[2 * j];
                hi += bv[2 * j + 1];
                if (FINAL) {
                    lo += dw * vv[2 * j];
                    hi += dw * vv[2 * j + 1];
                }
                if (STORE_C) dst[j] = __floats2half2_rn(lo, hi);
                if (STAT >= 0) {
                    s += lo + hi;
                    q += lo * lo + hi * hi;
                }
            }
        }
    }
    if (STAT >= 0) {
        sds[tid] = (double)s;
        sds[256 + tid] = (double)q;
        __syncthreads();
        for (int o = 128; o > 0; o >>= 1) {
            if (tid < o) {
                sds[tid] += sds[tid + o];
                sds[256 + tid] += sds[256 + tid + o];
            }
            __syncthreads();
        }
        if (tid == 0) {
            atomicAdd(&g_scal[STAT], sds[0]);
            atomicAdd(&g_scal[STAT + 1], sds[256]);
        }
    }
}

// From LN1 stats: a_k = inv*ln1w_k; c_k = ln1b_k - mean*a_k;
// g_avec = a;  g_dvec = (a∘b1 + c) @ W2.
__global__ __launch_bounds__(256) void k_prep(const float* __restrict__ lnw,
                                              const float* __restrict__ lnb,
                                              const float* __restrict__ b1,
                                              const float* __restrict__ W2, int M) {
    __shared__ float cs[HDIM];
    int t = threadIdx.x;
    double nn = (double)M * HDIM;
    double mm = g_scal[0] / nn;
    double var = g_scal[1] / nn - mm * mm;
    float mean = (float)mm;
    float inv = 1.f / ((float)sqrt(var) + EPS);
    float a = inv * lnw[t];
    float c = lnb[t] - mean * a;
    g_avec[t] = a;
    cs[t] = a * b1[t] + c;
    __syncthreads();
    float v = 0.f;
    for (int k = 0; k < HDIM; k++) v += cs[k] * W2[k * HDIM + t];
    g_dvec[t] = v;
}

// Wc[k][n] = sum_j W1[k][j] * a[j] * W2[j][n].  Grid: 256 blocks (n), 128 thr (k).
__global__ __launch_bounds__(128) void k_wc(const float* __restrict__ W1,
                                            const float* __restrict__ W2) {
    __shared__ float w2a[HDIM];
    int n = blockIdx.x, t = threadIdx.x;
    w2a[t] = g_avec[t] * W2[t * HDIM + n];
    w2a[t + 128] = g_avec[t + 128] * W2[(t + 128) * HDIM + n];
    __syncthreads();
    float s = 0.f;
    const float* w1r = W1 + t * HDIM;
#pragma unroll 8
    for (int j = 0; j < HDIM; j++) s += w1r[j] * w2a[j];
    g_Wc[t * HDIM + n] = s;
}

// Final graph LayerNorm: read fp16 hout, write fp32 out (evict-first).
__global__ __launch_bounds__(256) void k_ln2h(const __half* __restrict__ hout,
                                              const float* __restrict__ w,
                                              const float* __restrict__ b,
                                              float* __restrict__ out, int n8) {
    int i = blockIdx.x * blockDim.x + threadIdx.x;
    if (i >= n8) return;
    double n = (double)n8 * 8.0;
    double m = g_scal[2] / n;
    double var = g_scal[3] / n - m * m;
    float mean = (float)m;
    float inv = 1.f / ((float)sqrt(var) + EPS);
    uint4 u = __ldcs((const uint4*)hout + i);
    int c8 = (i & 31) * 8;
    float4 w0 = *(const float4*)(w + c8);
    float4 w1 = *(const float4*)(w + c8 + 4);
    float4 b0 = *(const float4*)(b + c8);
    float4 b1 = *(const float4*)(b + c8 + 4);
    float2 f0 = __half22float2(*(__half2*)&u.x);
    float2 f1 = __half22float2(*(__half2*)&u.y);
    float2 f2 = __half22float2(*(__half2*)&u.z);
    float2 f3 = __half22float2(*(__half2*)&u.w);
    float4 o0, o1;
    o0.x = (f0.x - mean) * inv * w0.x + b0.x;
    o0.y = (f0.y - mean) * inv * w0.y + b0.y;
    o0.z = (f1.x - mean) * inv * w0.z + b0.z;
    o0.w = (f1.y - mean) * inv * w0.w + b0.w;
    o1.x = (f2.x - mean) * inv * w1.x + b1.x;
    o1.y = (f2.y - mean) * inv * w1.y + b1.y;
    o1.z = (f3.x - mean) * inv * w1.z + b1.z;
    o1.w = (f3.y - mean) * inv * w1.w + b1.w;
    __stcs((float4*)out + 2 * i, o0);
    __stcs((float4*)out + 2 * i + 1, o1);
}

extern "C" void kernel_launch(void* const* d_in, const int* in_sizes, int n_in,
                              void* d_out, int out_size) {
    const float* x = (const float*)d_in[0];
    const int* ei[4] = {(const int*)d_in[1], (const int*)d_in[3],
                        (const int*)d_in[5], (const int*)d_in[7]};
    const float* ew[4] = {(const float*)d_in[2], (const float*)d_in[4],
                          (const float*)d_in[6], (const float*)d_in[8]};
    const float* W1 = (const float*)d_in[9];
    const float* b1 = (const float*)d_in[10];
    const float* W2 = (const float*)d_in[11];
    const float* b2 = (const float*)d_in[12];
    const float* ln1w = (const float*)d_in[13];
    const float* ln1b = (const float*)d_in[14];
    const float* ln2w = (const float*)d_in[15];
    const float* ln2b = (const float*)d_in[16];

    int N = in_sizes[0] / F_IN;
    int E = in_sizes[1] / 2;
    int n2 = N * F_IN / 2;
    int n8 = N * HDIM / 8;

    __half *xh, *aggh, *agg2h, *hout;
    float *dvec, *degw, *Wc;
    int *rowptr, *pos, *deg;
    cudaGetSymbolAddress((void**)&xh, g_xh);
    cudaGetSymbolAddress((void**)&aggh, g_aggh);
    cudaGetSymbolAddress((void**)&agg2h, g_agg2h);
    cudaGetSymbolAddress((void**)&hout, g_hout);
    cudaGetSymbolAddress((void**)&dvec, g_dvec);
    cudaGetSymbolAddress((void**)&degw, g_degw);
    cudaGetSymbolAddress((void**)&Wc, g_Wc);
    cudaGetSymbolAddress((void**)&rowptr, g_rowptr);
    cudaGetSymbolAddress((void**)&pos, g_pos);
    cudaGetSymbolAddress((void**)&deg, g_deg);
    float* out = (float*)d_out;

    int e4Blocks = (4 * E + 255) / 256;
    int scanB = (N + 1023) / 1024;
    dim3 gbig(HDIM / 128, (N + 127) / 128);

    // ---- CSR build ----
    k_convert_zdeg<<<(n2 + 255) / 256, 256>>>(x, xh, n2, deg, N);
    k_hist_all<<<e4Blocks, 256>>>(ei[0], ei[1], ei[2], ei[3], deg, E);
    k_scan1z<<<scanB, 1024>>>(deg, rowptr, N);
    k_scan3b<<<scanB, 1024>>>(rowptr, pos, deg, N);
    k_fill_all<<<e4Blocks, 256>>>(ei[0], ew[0], ei[1], ew[1], ei[2], ew[2],
                                  ei[3], ew[3], pos, E);

    // ---- Two 128-d gathers: agg1 = Adj@x, agg2 = Adj@agg1 (+degw) ----
    k_gather128<false><<<(N + 1) / 2, 64>>>((const uint2*)xh, rowptr, aggh,
                                            nullptr, N);
    k_gather128<true><<<(N + 1) / 2, 64>>>((const uint2*)aggh, rowptr, agg2h,
                                           degw, N);

    // ---- GEMM1 stats only (h1 never materialized) ----
    k_gemm_big<F_IN, false, 0, false><<<gbig, 256>>>(aggh, W1, b1, nullptr,
                                                     nullptr, nullptr, N);
    // ---- Fold LN1: a, v, Wc ----
    k_prep<<<1, 256>>>(ln1w, ln1b, b1, W2, N);
    k_wc<<<HDIM, 128>>>(W1, W2);

    // ---- Final GEMM: out2 = agg2@Wc + degw⊗v + b2 (+LN2 stats, fp16 out) ----
    k_gemm_big<F_IN, true, 2, true><<<gbig, 256>>>(agg2h, Wc, b2, degw,
                                                   dvec, hout, N);
    k_ln2h<<<(n8 + 255) / 256, 256>>>(hout, ln2w, ln2b, out, n8);
}